// round 10
// baseline (speedup 1.0000x reference)
#include <cuda_runtime.h>
#include <cstdint>

#define D_DIM  448
#define MTOT   32768
#define BM     128
#define BN     112
#define BK     32
#define NSTG   3
#define A_STRIDE 36                        // conflict-free scalar frag LDS
#define B_STRIDE 40                        // conflict-free v4 frag LDS
#define AS_F   (BM * A_STRIDE)             // 4608
#define BS_F   (BN * B_STRIDE)             // 4480
#define STG_F  (AS_F + BS_F)               // 9088
#define SMEM_BYTES (NSTG * STG_F * 4)      // 109056 -> 2 CTAs/SM

// W_eff transposed [n][k_perm], tf32-rounded.
// k16-interleave: j = k & 15 -> pos = 4*(j&3) + (j>>2), so a v4 at float
// offset (16blk + 4t) holds logical (k0+t, k0+t+4, k0+8+t, k0+8+t+4):
// the B fragments for BOTH k8 sub-steps of the k16 block.
__device__ __align__(16) float g_W[D_DIM * D_DIM];

// ---- helpers ----------------------------------------------------------------
__device__ __forceinline__ uint32_t smem_u32(const void* p) {
    uint32_t a;
    asm("{ .reg .u64 t; cvta.to.shared.u64 t, %1; cvt.u32.u64 %0, t; }" : "=r"(a) : "l"(p));
    return a;
}
__device__ __forceinline__ uint32_t f2tf32(float f) {
    uint32_t r;
    asm("cvt.rna.tf32.f32 %0, %1;" : "=r"(r) : "f"(f));
    return r;
}
__device__ __forceinline__ void mma_tf32(float* c, const uint32_t* a, uint32_t b0, uint32_t b1) {
    asm volatile(
        "mma.sync.aligned.m16n8k8.row.col.f32.tf32.tf32.f32 "
        "{%0,%1,%2,%3}, {%4,%5,%6,%7}, {%8,%9}, {%0,%1,%2,%3};"
        : "+f"(c[0]), "+f"(c[1]), "+f"(c[2]), "+f"(c[3])
        : "r"(a[0]), "r"(a[1]), "r"(a[2]), "r"(a[3]), "r"(b0), "r"(b1));
}
#define CP16(dst, src) \
    asm volatile("cp.async.cg.shared.global [%0], [%1], 16;" :: "r"(dst), "l"(src) : "memory")
#define CP_COMMIT() asm volatile("cp.async.commit_group;" ::: "memory")
#define CP_WAIT1()  asm volatile("cp.async.wait_group 1;" ::: "memory")

// ---------------------------------------------------------------------------
// Prep: W_eff = (Wq*diagA + Wk*diagB + Wv*diagC) @ Wo, transposed + k16-
// interleaved + tf32 into g_W. 32x32 tiles, grid (14,14), 256 threads,
// register-prefetched global loads. (R8 structure, new permutation.)
// ---------------------------------------------------------------------------
__global__ void __launch_bounds__(256) weff_kernel(const float* __restrict__ Wq,
                                                   const float* __restrict__ Wk,
                                                   const float* __restrict__ Wv,
                                                   const float* __restrict__ Wo,
                                                   const float* __restrict__ A,
                                                   const float* __restrict__ Bm,
                                                   const float* __restrict__ C) {
    __shared__ float dg[3][D_DIM];
    __shared__ float Ms[32][33];
    __shared__ float Ws[32][33];
    const int tid = threadIdx.x;
    for (int i = tid; i < D_DIM; i += 256) {
        dg[0][i] = A[(size_t)i * D_DIM + i];
        dg[1][i] = Bm[(size_t)i * D_DIM + i];
        dg[2][i] = C[(size_t)i * D_DIM + i];
    }

    const int ty = tid >> 4, tx = tid & 15;
    const int k0 = blockIdx.y * 32;
    const int n0 = blockIdx.x * 32;
    const int lrow = tid >> 3;
    const int lc4  = (tid & 7) * 4;

    const size_t qoff = (size_t)(k0 + lrow) * D_DIM + lc4;
    const size_t ooff = (size_t)lrow * D_DIM + n0 + lc4;

    float4 pq = *reinterpret_cast<const float4*>(Wq + qoff);
    float4 pk = *reinterpret_cast<const float4*>(Wk + qoff);
    float4 pv = *reinterpret_cast<const float4*>(Wv + qoff);
    float4 po = *reinterpret_cast<const float4*>(Wo + ooff);
    __syncthreads();

    float acc[2][2] = {};
    for (int kt = 0; kt < D_DIM; kt += 32) {
        {
            const float4 da = *reinterpret_cast<const float4*>(&dg[0][kt + lc4]);
            const float4 db = *reinterpret_cast<const float4*>(&dg[1][kt + lc4]);
            const float4 dc = *reinterpret_cast<const float4*>(&dg[2][kt + lc4]);
            Ms[lrow][lc4 + 0] = pq.x * da.x + pk.x * db.x + pv.x * dc.x;
            Ms[lrow][lc4 + 1] = pq.y * da.y + pk.y * db.y + pv.y * dc.y;
            Ms[lrow][lc4 + 2] = pq.z * da.z + pk.z * db.z + pv.z * dc.z;
            Ms[lrow][lc4 + 3] = pq.w * da.w + pk.w * db.w + pv.w * dc.w;
            Ws[lrow][lc4 + 0] = po.x; Ws[lrow][lc4 + 1] = po.y;
            Ws[lrow][lc4 + 2] = po.z; Ws[lrow][lc4 + 3] = po.w;
        }
        __syncthreads();

        if (kt + 32 < D_DIM) {
            pq = *reinterpret_cast<const float4*>(Wq + qoff + kt + 32);
            pk = *reinterpret_cast<const float4*>(Wk + qoff + kt + 32);
            pv = *reinterpret_cast<const float4*>(Wv + qoff + kt + 32);
            po = *reinterpret_cast<const float4*>(Wo + ooff + (size_t)(kt + 32) * D_DIM);
        }

#pragma unroll
        for (int kk = 0; kk < 32; kk++) {
            const float a0 = Ms[ty][kk],      a1 = Ms[ty + 16][kk];
            const float b0 = Ws[kk][tx],      b1 = Ws[kk][tx + 16];
            acc[0][0] += a0 * b0; acc[0][1] += a0 * b1;
            acc[1][0] += a1 * b0; acc[1][1] += a1 * b1;
        }
        __syncthreads();
    }
#pragma unroll
    for (int i = 0; i < 2; i++) {
        const int k = k0 + ty + i * 16;
        const int j = k & 15;
        const int kp = (k & ~15) | (4 * (j & 3) + (j >> 2));
#pragma unroll
        for (int jj = 0; jj < 2; jj++) {
            const int n = n0 + tx + jj * 16;
            g_W[(size_t)n * D_DIM + kp] = __uint_as_float(f2tf32(acc[i][jj]));
        }
    }
}

// ---------------------------------------------------------------------------
// Main GEMM: out = x @ W_eff, tf32 mma.sync.
// R7 config: BM=128, BN=112, BK=32, NSTG=3, 256 threads (8 warps, 4m x 2n),
// warp tile 32x56, single sync/iter. NEW: v4 B-fragment loads (k16 interleave).
// ---------------------------------------------------------------------------
__global__ void __launch_bounds__(256, 2) gemm_tf32_kernel(const float* __restrict__ x,
                                                           float* __restrict__ out) {
    extern __shared__ __align__(16) float smem[];

    const int tid   = threadIdx.x;
    const int wid   = tid >> 5;
    const int lane  = tid & 31;
    const int g     = lane >> 2;
    const int t     = lane & 3;
    const int warpM = wid & 3;
    const int warpN = wid >> 2;

    const int m0 = blockIdx.y * BM;
    const int n0 = blockIdx.x * BN;

    const uint32_t smem_base = smem_u32(smem);

    float acc[2][7][4];
#pragma unroll
    for (int i = 0; i < 2; i++)
#pragma unroll
        for (int j = 0; j < 7; j++)
#pragma unroll
            for (int q = 0; q < 4; q++) acc[i][j][q] = 0.f;

    auto load_stage = [&](int s, int kt) {
        const uint32_t aBase = smem_base + (uint32_t)(s * STG_F) * 4u;
        const uint32_t bBase = aBase + (uint32_t)AS_F * 4u;
#pragma unroll
        for (int j = 0; j < 4; j++) {
            const int id  = tid + j * 256;
            const int row = id >> 3;
            const int c   = id & 7;
            CP16(aBase + (uint32_t)(row * A_STRIDE + c * 4) * 4u,
                 x + (size_t)(m0 + row) * D_DIM + kt + c * 4);
        }
#pragma unroll
        for (int j = 0; j < 3; j++) {
            const int id  = tid + j * 256;
            const int row = id >> 3;
            const int c   = id & 7;
            CP16(bBase + (uint32_t)(row * B_STRIDE + c * 4) * 4u,
                 g_W + (size_t)(n0 + row) * D_DIM + kt + c * 4);
        }
        if (tid < 128) {
            const int id  = tid + 768;
            const int row = id >> 3;
            const int c   = id & 7;
            CP16(bBase + (uint32_t)(row * B_STRIDE + c * 4) * 4u,
                 g_W + (size_t)(n0 + row) * D_DIM + kt + c * 4);
        }
    };

    load_stage(0, 0);
    CP_COMMIT();
    load_stage(1, BK);
    CP_COMMIT();

    const int NIT = D_DIM / BK;   // 14
#pragma unroll 1
    for (int it = 0; it < NIT; it++) {
        CP_WAIT1();
        __syncthreads();

        if (it + 2 < NIT) load_stage((it + 2) % NSTG, (it + 2) * BK);
        CP_COMMIT();

        const float* As = smem + (it % NSTG) * STG_F;
        const float* Bs = As + AS_F;
        const float* Arow = As + (warpM * 32 + g) * A_STRIDE;
        const float* Brow = Bs + (warpN * 56 + g) * B_STRIDE;

#pragma unroll
        for (int kk2 = 0; kk2 < 2; kk2++) {          // two k16 blocks per BK=32
            // one v4 per ni covers B fragments of BOTH k8 sub-steps
            float4 bv[7];
#pragma unroll
            for (int ni = 0; ni < 7; ni++)
                bv[ni] = *reinterpret_cast<const float4*>(
                    Brow + ni * 8 * B_STRIDE + kk2 * 16 + 4 * t);

#pragma unroll
            for (int sb = 0; sb < 2; sb++) {         // k8 sub-steps
                const int k0 = kk2 * 16 + sb * 8;
                uint32_t af[2][4];
#pragma unroll
                for (int mi = 0; mi < 2; mi++) {
                    const float* Ar = Arow + mi * 16 * A_STRIDE;
                    af[mi][0] = f2tf32(Ar[k0 + t]);
                    af[mi][1] = f2tf32(Ar[8 * A_STRIDE + k0 + t]);
                    af[mi][2] = f2tf32(Ar[k0 + t + 4]);
                    af[mi][3] = f2tf32(Ar[8 * A_STRIDE + k0 + t + 4]);
                }
#pragma unroll
                for (int ni = 0; ni < 7; ni++) {
                    const uint32_t b0 = __float_as_uint(sb ? bv[ni].z : bv[ni].x);
                    const uint32_t b1 = __float_as_uint(sb ? bv[ni].w : bv[ni].y);
                    mma_tf32(acc[0][ni], af[0], b0, b1);
                    mma_tf32(acc[1][ni], af[1], b0, b1);
                }
            }
        }
        // no trailing sync: next iteration's top sync provides the ordering
    }

    // ---- epilogue: rows (g, g+8), cols (2t, 2t+1) per (mi, ni)
#pragma unroll
    for (int mi = 0; mi < 2; mi++) {
        const int r0 = m0 + warpM * 32 + mi * 16 + g;
#pragma unroll
        for (int ni = 0; ni < 7; ni++) {
            const int c0 = n0 + warpN * 56 + ni * 8 + 2 * t;
            float2 v0, v1;
            v0.x = acc[mi][ni][0]; v0.y = acc[mi][ni][1];
            v1.x = acc[mi][ni][2]; v1.y = acc[mi][ni][3];
            *reinterpret_cast<float2*>(out + (size_t)r0 * D_DIM + c0)       = v0;
            *reinterpret_cast<float2*>(out + (size_t)(r0 + 8) * D_DIM + c0) = v1;
        }
    }
}

// ---------------------------------------------------------------------------
extern "C" void kernel_launch(void* const* d_in, const int* in_sizes, int n_in,
                              void* d_out, int out_size) {
    const float* x  = (const float*)d_in[0];
    const float* Wq = (const float*)d_in[1];
    const float* Wk = (const float*)d_in[2];
    const float* Wv = (const float*)d_in[3];
    const float* Wo = (const float*)d_in[4];
    const float* A  = (const float*)d_in[5];
    const float* B  = (const float*)d_in[6];
    const float* C  = (const float*)d_in[7];

    cudaFuncSetAttribute(gemm_tf32_kernel, cudaFuncAttributeMaxDynamicSharedMemorySize,
                         SMEM_BYTES);

    weff_kernel<<<dim3(D_DIM / 32, D_DIM / 32), 256>>>(Wq, Wk, Wv, Wo, A, B, C);
    gemm_tf32_kernel<<<dim3(D_DIM / BN, MTOT / BM), 256, SMEM_BYTES>>>(x, (float*)d_out);
}

// round 11
// speedup vs baseline: 1.1438x; 1.1438x over previous
#include <cuda_runtime.h>
#include <cstdint>

#define D_DIM  448
#define MTOT   32768
#define BM     128
#define BN     112
#define BK     32
#define NSTG   3
#define A_STRIDE 36                        // conflict-free scalar frag LDS
#define B_STRIDE 40                        // conflict-free v2 frag LDS
#define AS_F   (BM * A_STRIDE)             // 4608
#define BS_F   (BN * B_STRIDE)             // 4480
#define STG_F  (AS_F + BS_F)               // 9088
#define SMEM_BYTES (NSTG * STG_F * 4)      // 109056 -> 2 CTAs/SM

// W_eff transposed [n][k_perm], tf32-rounded. perm in 8-block: j<4 ? 2j : 2(j-4)+1
// (so mma B-fragment pair (t, t+4) sits at adjacent floats -> ld.shared.v2)
__device__ __align__(16) float g_W[D_DIM * D_DIM];

// ---- helpers ----------------------------------------------------------------
__device__ __forceinline__ uint32_t smem_u32(const void* p) {
    uint32_t a;
    asm("{ .reg .u64 t; cvta.to.shared.u64 t, %1; cvt.u32.u64 %0, t; }" : "=r"(a) : "l"(p));
    return a;
}
__device__ __forceinline__ uint32_t f2tf32(float f) {
    uint32_t r;
    asm("cvt.rna.tf32.f32 %0, %1;" : "=r"(r) : "f"(f));
    return r;
}
__device__ __forceinline__ void mma_tf32(float* c, const uint32_t* a, uint32_t b0, uint32_t b1) {
    asm volatile(
        "mma.sync.aligned.m16n8k8.row.col.f32.tf32.tf32.f32 "
        "{%0,%1,%2,%3}, {%4,%5,%6,%7}, {%8,%9}, {%0,%1,%2,%3};"
        : "+f"(c[0]), "+f"(c[1]), "+f"(c[2]), "+f"(c[3])
        : "r"(a[0]), "r"(a[1]), "r"(a[2]), "r"(a[3]), "r"(b0), "r"(b1));
}
#define CP16(dst, src) \
    asm volatile("cp.async.cg.shared.global [%0], [%1], 16;" :: "r"(dst), "l"(src) : "memory")
#define CP_COMMIT() asm volatile("cp.async.commit_group;" ::: "memory")
#define CP_WAIT1()  asm volatile("cp.async.wait_group 1;" ::: "memory")

// ---------------------------------------------------------------------------
// Prep (R8, measured best): W_eff = (Wq*diagA + Wk*diagB + Wv*diagC) @ Wo,
// transposed + 8-block-k-permuted + tf32 into g_W. 32x32 tiles, grid (14,14),
// 256 threads, register-prefetched global loads.
// ---------------------------------------------------------------------------
__global__ void __launch_bounds__(256) weff_kernel(const float* __restrict__ Wq,
                                                   const float* __restrict__ Wk,
                                                   const float* __restrict__ Wv,
                                                   const float* __restrict__ Wo,
                                                   const float* __restrict__ A,
                                                   const float* __restrict__ Bm,
                                                   const float* __restrict__ C) {
    __shared__ float dg[3][D_DIM];
    __shared__ float Ms[32][33];
    __shared__ float Ws[32][33];
    const int tid = threadIdx.x;
    for (int i = tid; i < D_DIM; i += 256) {
        dg[0][i] = A[(size_t)i * D_DIM + i];
        dg[1][i] = Bm[(size_t)i * D_DIM + i];
        dg[2][i] = C[(size_t)i * D_DIM + i];
    }

    const int ty = tid >> 4, tx = tid & 15;
    const int k0 = blockIdx.y * 32;
    const int n0 = blockIdx.x * 32;
    const int lrow = tid >> 3;
    const int lc4  = (tid & 7) * 4;

    const size_t qoff = (size_t)(k0 + lrow) * D_DIM + lc4;
    const size_t ooff = (size_t)lrow * D_DIM + n0 + lc4;

    float4 pq = *reinterpret_cast<const float4*>(Wq + qoff);
    float4 pk = *reinterpret_cast<const float4*>(Wk + qoff);
    float4 pv = *reinterpret_cast<const float4*>(Wv + qoff);
    float4 po = *reinterpret_cast<const float4*>(Wo + ooff);
    __syncthreads();

    float acc[2][2] = {};
    for (int kt = 0; kt < D_DIM; kt += 32) {
        {
            const float4 da = *reinterpret_cast<const float4*>(&dg[0][kt + lc4]);
            const float4 db = *reinterpret_cast<const float4*>(&dg[1][kt + lc4]);
            const float4 dc = *reinterpret_cast<const float4*>(&dg[2][kt + lc4]);
            Ms[lrow][lc4 + 0] = pq.x * da.x + pk.x * db.x + pv.x * dc.x;
            Ms[lrow][lc4 + 1] = pq.y * da.y + pk.y * db.y + pv.y * dc.y;
            Ms[lrow][lc4 + 2] = pq.z * da.z + pk.z * db.z + pv.z * dc.z;
            Ms[lrow][lc4 + 3] = pq.w * da.w + pk.w * db.w + pv.w * dc.w;
            Ws[lrow][lc4 + 0] = po.x; Ws[lrow][lc4 + 1] = po.y;
            Ws[lrow][lc4 + 2] = po.z; Ws[lrow][lc4 + 3] = po.w;
        }
        __syncthreads();

        if (kt + 32 < D_DIM) {
            pq = *reinterpret_cast<const float4*>(Wq + qoff + kt + 32);
            pk = *reinterpret_cast<const float4*>(Wk + qoff + kt + 32);
            pv = *reinterpret_cast<const float4*>(Wv + qoff + kt + 32);
            po = *reinterpret_cast<const float4*>(Wo + ooff + (size_t)(kt + 32) * D_DIM);
        }

#pragma unroll
        for (int kk = 0; kk < 32; kk++) {
            const float a0 = Ms[ty][kk],      a1 = Ms[ty + 16][kk];
            const float b0 = Ws[kk][tx],      b1 = Ws[kk][tx + 16];
            acc[0][0] += a0 * b0; acc[0][1] += a0 * b1;
            acc[1][0] += a1 * b0; acc[1][1] += a1 * b1;
        }
        __syncthreads();
    }
#pragma unroll
    for (int i = 0; i < 2; i++) {
        const int k = k0 + ty + i * 16;
        const int j = k & 7;
        const int kp = (k & ~7) | (j < 4 ? 2 * j : 2 * (j - 4) + 1);
#pragma unroll
        for (int jj = 0; jj < 2; jj++) {
            const int n = n0 + tx + jj * 16;
            g_W[(size_t)n * D_DIM + kp] = __uint_as_float(f2tf32(acc[i][jj]));
        }
    }
}

// ---------------------------------------------------------------------------
// Main GEMM (R7, measured best): out = x @ W_eff, tf32 mma.sync.
// BM=128, BN=112, BK=32, NSTG=3, 256 threads (8 warps, 4m x 2n),
// warp tile 32x56, scalar A frags + v2 B frags, single sync per iteration.
// ---------------------------------------------------------------------------
__global__ void __launch_bounds__(256, 2) gemm_tf32_kernel(const float* __restrict__ x,
                                                           float* __restrict__ out) {
    extern __shared__ __align__(16) float smem[];

    const int tid   = threadIdx.x;
    const int wid   = tid >> 5;
    const int lane  = tid & 31;
    const int g     = lane >> 2;
    const int t     = lane & 3;
    const int warpM = wid & 3;
    const int warpN = wid >> 2;

    const int m0 = blockIdx.y * BM;
    const int n0 = blockIdx.x * BN;

    const uint32_t smem_base = smem_u32(smem);

    float acc[2][7][4];
#pragma unroll
    for (int i = 0; i < 2; i++)
#pragma unroll
        for (int j = 0; j < 7; j++)
#pragma unroll
            for (int q = 0; q < 4; q++) acc[i][j][q] = 0.f;

    auto load_stage = [&](int s, int kt) {
        const uint32_t aBase = smem_base + (uint32_t)(s * STG_F) * 4u;
        const uint32_t bBase = aBase + (uint32_t)AS_F * 4u;
#pragma unroll
        for (int j = 0; j < 4; j++) {
            const int id  = tid + j * 256;
            const int row = id >> 3;
            const int c   = id & 7;
            CP16(aBase + (uint32_t)(row * A_STRIDE + c * 4) * 4u,
                 x + (size_t)(m0 + row) * D_DIM + kt + c * 4);
        }
#pragma unroll
        for (int j = 0; j < 3; j++) {
            const int id  = tid + j * 256;
            const int row = id >> 3;
            const int c   = id & 7;
            CP16(bBase + (uint32_t)(row * B_STRIDE + c * 4) * 4u,
                 g_W + (size_t)(n0 + row) * D_DIM + kt + c * 4);
        }
        if (tid < 128) {
            const int id  = tid + 768;
            const int row = id >> 3;
            const int c   = id & 7;
            CP16(bBase + (uint32_t)(row * B_STRIDE + c * 4) * 4u,
                 g_W + (size_t)(n0 + row) * D_DIM + kt + c * 4);
        }
    };

    load_stage(0, 0);
    CP_COMMIT();
    load_stage(1, BK);
    CP_COMMIT();

    const int NIT = D_DIM / BK;   // 14
#pragma unroll 1
    for (int it = 0; it < NIT; it++) {
        CP_WAIT1();
        __syncthreads();

        if (it + 2 < NIT) load_stage((it + 2) % NSTG, (it + 2) * BK);
        CP_COMMIT();

        const float* As = smem + (it % NSTG) * STG_F;
        const float* Bs = As + AS_F;
        const float* Arow = As + (warpM * 32 + g) * A_STRIDE;
        const float* Brow = Bs + (warpN * 56 + g) * B_STRIDE;

#pragma unroll
        for (int kk = 0; kk < 4; kk++) {
            const int k0 = kk * 8;
            uint32_t af[2][4];
#pragma unroll
            for (int mi = 0; mi < 2; mi++) {
                const float* Ar = Arow + mi * 16 * A_STRIDE;
                af[mi][0] = f2tf32(Ar[k0 + t]);
                af[mi][1] = f2tf32(Ar[8 * A_STRIDE + k0 + t]);
                af[mi][2] = f2tf32(Ar[k0 + t + 4]);
                af[mi][3] = f2tf32(Ar[8 * A_STRIDE + k0 + t + 4]);
            }
#pragma unroll
            for (int ni = 0; ni < 7; ni++) {
                // permuted layout: logical (k0+t, k0+t+4) at floats (k0+2t, k0+2t+1)
                const float2 bv = *reinterpret_cast<const float2*>(
                    Brow + ni * 8 * B_STRIDE + k0 + 2 * t);
                const uint32_t b0 = __float_as_uint(bv.x);
                const uint32_t b1 = __float_as_uint(bv.y);
                mma_tf32(acc[0][ni], af[0], b0, b1);
                mma_tf32(acc[1][ni], af[1], b0, b1);
            }
        }
        // no trailing sync: next iteration's top sync provides the ordering
    }

    // ---- epilogue: rows (g, g+8), cols (2t, 2t+1) per (mi, ni)
#pragma unroll
    for (int mi = 0; mi < 2; mi++) {
        const int r0 = m0 + warpM * 32 + mi * 16 + g;
#pragma unroll
        for (int ni = 0; ni < 7; ni++) {
            const int c0 = n0 + warpN * 56 + ni * 8 + 2 * t;
            float2 v0, v1;
            v0.x = acc[mi][ni][0]; v0.y = acc[mi][ni][1];
            v1.x = acc[mi][ni][2]; v1.y = acc[mi][ni][3];
            *reinterpret_cast<float2*>(out + (size_t)r0 * D_DIM + c0)       = v0;
            *reinterpret_cast<float2*>(out + (size_t)(r0 + 8) * D_DIM + c0) = v1;
        }
    }
}

// ---------------------------------------------------------------------------
extern "C" void kernel_launch(void* const* d_in, const int* in_sizes, int n_in,
                              void* d_out, int out_size) {
    const float* x  = (const float*)d_in[0];
    const float* Wq = (const float*)d_in[1];
    const float* Wk = (const float*)d_in[2];
    const float* Wv = (const float*)d_in[3];
    const float* Wo = (const float*)d_in[4];
    const float* A  = (const float*)d_in[5];
    const float* B  = (const float*)d_in[6];
    const float* C  = (const float*)d_in[7];

    cudaFuncSetAttribute(gemm_tf32_kernel, cudaFuncAttributeMaxDynamicSharedMemorySize,
                         SMEM_BYTES);

    weff_kernel<<<dim3(D_DIM / 32, D_DIM / 32), 256>>>(Wq, Wk, Wv, Wo, A, B, C);
    gemm_tf32_kernel<<<dim3(D_DIM / BN, MTOT / BM), 256, SMEM_BYTES>>>(x, (float*)d_out);
}

// round 12
// speedup vs baseline: 1.5495x; 1.3547x over previous
#include <cuda_runtime.h>
#include <cuda_fp16.h>
#include <cstdint>

#define D_DIM  448
#define MTOT   32768
#define BM     128
#define BN     112
#define BK     32
#define NSTG   3
#define AS     40                          // A smem stride in floats (conflict-free v2)
#define BSB    96                          // B smem row stride in BYTES (48 halves, conflict-free v2)
#define A_STAGE_BYTES (BM * AS * 4)        // 20480
#define B_STAGE_BYTES (BN * BSB)           // 10752
#define STG_BYTES (A_STAGE_BYTES + B_STAGE_BYTES)   // 31232
#define SMEM_BYTES (NSTG * STG_BYTES)      // 93696 -> 2 CTAs/SM

// W_eff transposed [n][k_perm16] as fp16.
// k16-interleave: j=k&15 -> p = 4*((j&7)>>1) + 2*(j>>3) + (j&1), so one 8B load
// at half-offset 4t yields b0 = {k=2t, 2t+1} (low 4B) and b1 = {k=2t+8, 2t+9}.
__device__ __align__(16) __half g_Wh[D_DIM * D_DIM];

// ---- helpers ----------------------------------------------------------------
__device__ __forceinline__ uint32_t smem_u32(const void* p) {
    uint32_t a;
    asm("{ .reg .u64 t; cvta.to.shared.u64 t, %1; cvt.u32.u64 %0, t; }" : "=r"(a) : "l"(p));
    return a;
}
__device__ __forceinline__ uint32_t pack_h2(float lo, float hi) {
    __half2 h = __floats2half2_rn(lo, hi);
    return *reinterpret_cast<uint32_t*>(&h);
}
__device__ __forceinline__ void mma_f16(float* c, const uint32_t* a, uint32_t b0, uint32_t b1) {
    asm volatile(
        "mma.sync.aligned.m16n8k16.row.col.f32.f16.f16.f32 "
        "{%0,%1,%2,%3}, {%4,%5,%6,%7}, {%8,%9}, {%0,%1,%2,%3};"
        : "+f"(c[0]), "+f"(c[1]), "+f"(c[2]), "+f"(c[3])
        : "r"(a[0]), "r"(a[1]), "r"(a[2]), "r"(a[3]), "r"(b0), "r"(b1));
}
#define CP16(dst, src) \
    asm volatile("cp.async.cg.shared.global [%0], [%1], 16;" :: "r"(dst), "l"(src) : "memory")
#define CP_COMMIT() asm volatile("cp.async.commit_group;" ::: "memory")
#define CP_WAIT1()  asm volatile("cp.async.wait_group 1;" ::: "memory")

// ---------------------------------------------------------------------------
// Prep (R8 structure): W_eff = (Wq*diagA + Wk*diagB + Wv*diagC) @ Wo,
// transposed + k16-interleaved + fp16-rounded into g_Wh. 32x32 tiles,
// grid (14,14), 256 threads, register-prefetched global loads.
// ---------------------------------------------------------------------------
__global__ void __launch_bounds__(256) weff_kernel(const float* __restrict__ Wq,
                                                   const float* __restrict__ Wk,
                                                   const float* __restrict__ Wv,
                                                   const float* __restrict__ Wo,
                                                   const float* __restrict__ A,
                                                   const float* __restrict__ Bm,
                                                   const float* __restrict__ C) {
    __shared__ float dg[3][D_DIM];
    __shared__ float Ms[32][33];
    __shared__ float Ws[32][33];
    const int tid = threadIdx.x;
    for (int i = tid; i < D_DIM; i += 256) {
        dg[0][i] = A[(size_t)i * D_DIM + i];
        dg[1][i] = Bm[(size_t)i * D_DIM + i];
        dg[2][i] = C[(size_t)i * D_DIM + i];
    }

    const int ty = tid >> 4, tx = tid & 15;
    const int k0 = blockIdx.y * 32;
    const int n0 = blockIdx.x * 32;
    const int lrow = tid >> 3;
    const int lc4  = (tid & 7) * 4;

    const size_t qoff = (size_t)(k0 + lrow) * D_DIM + lc4;
    const size_t ooff = (size_t)lrow * D_DIM + n0 + lc4;

    float4 pq = *reinterpret_cast<const float4*>(Wq + qoff);
    float4 pk = *reinterpret_cast<const float4*>(Wk + qoff);
    float4 pv = *reinterpret_cast<const float4*>(Wv + qoff);
    float4 po = *reinterpret_cast<const float4*>(Wo + ooff);
    __syncthreads();

    float acc[2][2] = {};
    for (int kt = 0; kt < D_DIM; kt += 32) {
        {
            const float4 da = *reinterpret_cast<const float4*>(&dg[0][kt + lc4]);
            const float4 db = *reinterpret_cast<const float4*>(&dg[1][kt + lc4]);
            const float4 dc = *reinterpret_cast<const float4*>(&dg[2][kt + lc4]);
            Ms[lrow][lc4 + 0] = pq.x * da.x + pk.x * db.x + pv.x * dc.x;
            Ms[lrow][lc4 + 1] = pq.y * da.y + pk.y * db.y + pv.y * dc.y;
            Ms[lrow][lc4 + 2] = pq.z * da.z + pk.z * db.z + pv.z * dc.z;
            Ms[lrow][lc4 + 3] = pq.w * da.w + pk.w * db.w + pv.w * dc.w;
            Ws[lrow][lc4 + 0] = po.x; Ws[lrow][lc4 + 1] = po.y;
            Ws[lrow][lc4 + 2] = po.z; Ws[lrow][lc4 + 3] = po.w;
        }
        __syncthreads();

        if (kt + 32 < D_DIM) {
            pq = *reinterpret_cast<const float4*>(Wq + qoff + kt + 32);
            pk = *reinterpret_cast<const float4*>(Wk + qoff + kt + 32);
            pv = *reinterpret_cast<const float4*>(Wv + qoff + kt + 32);
            po = *reinterpret_cast<const float4*>(Wo + ooff + (size_t)(kt + 32) * D_DIM);
        }

#pragma unroll
        for (int kk = 0; kk < 32; kk++) {
            const float a0 = Ms[ty][kk],      a1 = Ms[ty + 16][kk];
            const float b0 = Ws[kk][tx],      b1 = Ws[kk][tx + 16];
            acc[0][0] += a0 * b0; acc[0][1] += a0 * b1;
            acc[1][0] += a1 * b0; acc[1][1] += a1 * b1;
        }
        __syncthreads();
    }
#pragma unroll
    for (int i = 0; i < 2; i++) {
        const int k = k0 + ty + i * 16;
        const int j = k & 15;
        const int kp = (k & ~15) | (4 * ((j & 7) >> 1) + 2 * (j >> 3) + (j & 1));
#pragma unroll
        for (int jj = 0; jj < 2; jj++) {
            const int n = n0 + tx + jj * 16;
            g_Wh[(size_t)n * D_DIM + kp] = __float2half_rn(acc[i][jj]);
        }
    }
}

// ---------------------------------------------------------------------------
// Main GEMM: out = x @ W_eff via fp16 mma.sync m16n8k16 (fp32 accum).
// BM=128, BN=112, BK=32, NSTG=3, 256 threads (8 warps, 4m x 2n),
// warp tile 32x56, single sync per iteration. A in fp32 smem (packed to
// f16x2 in-register), B in fp16 smem (k16-interleaved, one 8B load / frag).
// ---------------------------------------------------------------------------
__global__ void __launch_bounds__(256, 2) gemm_f16_kernel(const float* __restrict__ x,
                                                          float* __restrict__ out) {
    extern __shared__ __align__(16) char smem[];

    const int tid   = threadIdx.x;
    const int wid   = tid >> 5;
    const int lane  = tid & 31;
    const int g     = lane >> 2;
    const int t     = lane & 3;
    const int warpM = wid & 3;
    const int warpN = wid >> 2;

    const int m0 = blockIdx.y * BM;
    const int n0 = blockIdx.x * BN;

    const uint32_t smem_base = smem_u32(smem);

    float acc[2][7][4];
#pragma unroll
    for (int i = 0; i < 2; i++)
#pragma unroll
        for (int j = 0; j < 7; j++)
#pragma unroll
            for (int q = 0; q < 4; q++) acc[i][j][q] = 0.f;

    auto load_stage = [&](int s, int kt) {
        const uint32_t aBase = smem_base + (uint32_t)(s * STG_BYTES);
        const uint32_t bBase = aBase + (uint32_t)A_STAGE_BYTES;
        // A: 128 rows x 32 floats = 1024 16B chunks, 4 per thread
#pragma unroll
        for (int j = 0; j < 4; j++) {
            const int id  = tid + j * 256;
            const int row = id >> 3;
            const int c   = id & 7;
            CP16(aBase + (uint32_t)(row * (AS * 4) + c * 16),
                 x + (size_t)(m0 + row) * D_DIM + kt + c * 4);
        }
        // B: 112 rows x 32 halves (64B) = 448 16B chunks
        {
            const int row = tid >> 2;
            const int c   = tid & 3;
            CP16(bBase + (uint32_t)(row * BSB + c * 16),
                 (const char*)g_Wh + ((size_t)(n0 + row) * D_DIM + kt) * 2 + c * 16);
        }
        if (tid < 192) {
            const int id  = tid + 256;
            const int row = id >> 2;
            const int c   = id & 3;
            CP16(bBase + (uint32_t)(row * BSB + c * 16),
                 (const char*)g_Wh + ((size_t)(n0 + row) * D_DIM + kt) * 2 + c * 16);
        }
    };

    load_stage(0, 0);
    CP_COMMIT();
    load_stage(1, BK);
    CP_COMMIT();

    const int NIT = D_DIM / BK;   // 14
#pragma unroll 1
    for (int it = 0; it < NIT; it++) {
        CP_WAIT1();
        __syncthreads();

        if (it + 2 < NIT) load_stage((it + 2) % NSTG, (it + 2) * BK);
        CP_COMMIT();

        const char* stage = smem + (it % NSTG) * STG_BYTES;
        const float* Arow = reinterpret_cast<const float*>(stage)
                            + (warpM * 32 + g) * AS;
        const char* Brow  = stage + A_STAGE_BYTES + (warpN * 56 + g) * BSB;

#pragma unroll
        for (int kk2 = 0; kk2 < 2; kk2++) {    // two k16 blocks per BK=32
            const int k0 = kk2 * 16;
            uint32_t af[2][4];
#pragma unroll
            for (int mi = 0; mi < 2; mi++) {
                const float* Ar = Arow + mi * 16 * AS;
                const float2 x0 = *reinterpret_cast<const float2*>(Ar + k0 + 2 * t);
                const float2 x1 = *reinterpret_cast<const float2*>(Ar + 8 * AS + k0 + 2 * t);
                const float2 x2 = *reinterpret_cast<const float2*>(Ar + k0 + 2 * t + 8);
                const float2 x3 = *reinterpret_cast<const float2*>(Ar + 8 * AS + k0 + 2 * t + 8);
                af[mi][0] = pack_h2(x0.x, x0.y);
                af[mi][1] = pack_h2(x1.x, x1.y);
                af[mi][2] = pack_h2(x2.x, x2.y);
                af[mi][3] = pack_h2(x3.x, x3.y);
            }
#pragma unroll
            for (int ni = 0; ni < 7; ni++) {
                // interleaved layout: 8B at half-offset 4t = {k0+2t, k0+2t+1 | k0+2t+8, k0+2t+9}
                const uint2 bv = *reinterpret_cast<const uint2*>(
                    Brow + ni * 8 * BSB + kk2 * 32 + 8 * t);
                mma_f16(acc[0][ni], af[0], bv.x, bv.y);
                mma_f16(acc[1][ni], af[1], bv.x, bv.y);
            }
        }
        // no trailing sync: next iteration's top sync provides the ordering
    }

    // ---- epilogue: rows (g, g+8), cols (2t, 2t+1) per (mi, ni)
#pragma unroll
    for (int mi = 0; mi < 2; mi++) {
        const int r0 = m0 + warpM * 32 + mi * 16 + g;
#pragma unroll
        for (int ni = 0; ni < 7; ni++) {
            const int c0 = n0 + warpN * 56 + ni * 8 + 2 * t;
            float2 v0, v1;
            v0.x = acc[mi][ni][0]; v0.y = acc[mi][ni][1];
            v1.x = acc[mi][ni][2]; v1.y = acc[mi][ni][3];
            *reinterpret_cast<float2*>(out + (size_t)r0 * D_DIM + c0)       = v0;
            *reinterpret_cast<float2*>(out + (size_t)(r0 + 8) * D_DIM + c0) = v1;
        }
    }
}

// ---------------------------------------------------------------------------
extern "C" void kernel_launch(void* const* d_in, const int* in_sizes, int n_in,
                              void* d_out, int out_size) {
    const float* x  = (const float*)d_in[0];
    const float* Wq = (const float*)d_in[1];
    const float* Wk = (const float*)d_in[2];
    const float* Wv = (const float*)d_in[3];
    const float* Wo = (const float*)d_in[4];
    const float* A  = (const float*)d_in[5];
    const float* B  = (const float*)d_in[6];
    const float* C  = (const float*)d_in[7];

    cudaFuncSetAttribute(gemm_f16_kernel, cudaFuncAttributeMaxDynamicSharedMemorySize,
                         SMEM_BYTES);

    weff_kernel<<<dim3(D_DIM / 32, D_DIM / 32), 256>>>(Wq, Wk, Wv, Wo, A, B, C);
    gemm_f16_kernel<<<dim3(D_DIM / BN, MTOT / BM), 256, SMEM_BYTES>>>(x, (float*)d_out);
}

// round 13
// speedup vs baseline: 1.6519x; 1.0661x over previous
#include <cuda_runtime.h>
#include <cuda_fp16.h>
#include <cstdint>

#define D_DIM  448
#define MTOT   32768
#define BM     128
#define BN     112
#define BK     64
#define NSTG   2
#define AS     72                          // A smem stride in floats (v2 conflict-free: 36≡4 mod 16)
#define BSB    160                         // B smem row stride in BYTES (v2 conflict-free: 20≡4 mod 16)
#define A_STAGE_BYTES (BM * AS * 4)        // 36864
#define B_STAGE_BYTES (BN * BSB)           // 17920
#define STG_BYTES (A_STAGE_BYTES + B_STAGE_BYTES)   // 54784
#define SMEM_BYTES (NSTG * STG_BYTES)      // 109568 -> 2 CTAs/SM

// W_eff transposed [n][k_perm16] as fp16.
// k16-interleave: j=k&15 -> p = 4*((j&7)>>1) + 2*(j>>3) + (j&1): one 8B load at
// half-offset 4t yields b0={k0+2t,2t+1} (low 4B) and b1={k0+2t+8,2t+9} (high 4B).
__device__ __align__(16) __half g_Wh[D_DIM * D_DIM];

// ---- helpers ----------------------------------------------------------------
__device__ __forceinline__ uint32_t smem_u32(const void* p) {
    uint32_t a;
    asm("{ .reg .u64 t; cvta.to.shared.u64 t, %1; cvt.u32.u64 %0, t; }" : "=r"(a) : "l"(p));
    return a;
}
__device__ __forceinline__ uint32_t pack_h2(float lo, float hi) {
    __half2 h = __floats2half2_rn(lo, hi);
    return *reinterpret_cast<uint32_t*>(&h);
}
__device__ __forceinline__ void mma_f16(float* c, const uint32_t* a, uint32_t b0, uint32_t b1) {
    asm volatile(
        "mma.sync.aligned.m16n8k16.row.col.f32.f16.f16.f32 "
        "{%0,%1,%2,%3}, {%4,%5,%6,%7}, {%8,%9}, {%0,%1,%2,%3};"
        : "+f"(c[0]), "+f"(c[1]), "+f"(c[2]), "+f"(c[3])
        : "r"(a[0]), "r"(a[1]), "r"(a[2]), "r"(a[3]), "r"(b0), "r"(b1));
}
#define CP16(dst, src) \
    asm volatile("cp.async.cg.shared.global [%0], [%1], 16;" :: "r"(dst), "l"(src) : "memory")
#define CP_COMMIT() asm volatile("cp.async.commit_group;" ::: "memory")
#define CP_WAIT0()  asm volatile("cp.async.wait_group 0;" ::: "memory")

// ---------------------------------------------------------------------------
// Prep (R12, measured best): W_eff = (Wq*diagA + Wk*diagB + Wv*diagC) @ Wo,
// transposed + k16-interleaved + fp16 into g_Wh. 32x32 tiles, grid (14,14),
// 256 threads, register-prefetched global loads.
// ---------------------------------------------------------------------------
__global__ void __launch_bounds__(256) weff_kernel(const float* __restrict__ Wq,
                                                   const float* __restrict__ Wk,
                                                   const float* __restrict__ Wv,
                                                   const float* __restrict__ Wo,
                                                   const float* __restrict__ A,
                                                   const float* __restrict__ Bm,
                                                   const float* __restrict__ C) {
    __shared__ float dg[3][D_DIM];
    __shared__ float Ms[32][33];
    __shared__ float Ws[32][33];
    const int tid = threadIdx.x;
    for (int i = tid; i < D_DIM; i += 256) {
        dg[0][i] = A[(size_t)i * D_DIM + i];
        dg[1][i] = Bm[(size_t)i * D_DIM + i];
        dg[2][i] = C[(size_t)i * D_DIM + i];
    }

    const int ty = tid >> 4, tx = tid & 15;
    const int k0 = blockIdx.y * 32;
    const int n0 = blockIdx.x * 32;
    const int lrow = tid >> 3;
    const int lc4  = (tid & 7) * 4;

    const size_t qoff = (size_t)(k0 + lrow) * D_DIM + lc4;
    const size_t ooff = (size_t)lrow * D_DIM + n0 + lc4;

    float4 pq = *reinterpret_cast<const float4*>(Wq + qoff);
    float4 pk = *reinterpret_cast<const float4*>(Wk + qoff);
    float4 pv = *reinterpret_cast<const float4*>(Wv + qoff);
    float4 po = *reinterpret_cast<const float4*>(Wo + ooff);
    __syncthreads();

    float acc[2][2] = {};
    for (int kt = 0; kt < D_DIM; kt += 32) {
        {
            const float4 da = *reinterpret_cast<const float4*>(&dg[0][kt + lc4]);
            const float4 db = *reinterpret_cast<const float4*>(&dg[1][kt + lc4]);
            const float4 dc = *reinterpret_cast<const float4*>(&dg[2][kt + lc4]);
            Ms[lrow][lc4 + 0] = pq.x * da.x + pk.x * db.x + pv.x * dc.x;
            Ms[lrow][lc4 + 1] = pq.y * da.y + pk.y * db.y + pv.y * dc.y;
            Ms[lrow][lc4 + 2] = pq.z * da.z + pk.z * db.z + pv.z * dc.z;
            Ms[lrow][lc4 + 3] = pq.w * da.w + pk.w * db.w + pv.w * dc.w;
            Ws[lrow][lc4 + 0] = po.x; Ws[lrow][lc4 + 1] = po.y;
            Ws[lrow][lc4 + 2] = po.z; Ws[lrow][lc4 + 3] = po.w;
        }
        __syncthreads();

        if (kt + 32 < D_DIM) {
            pq = *reinterpret_cast<const float4*>(Wq + qoff + kt + 32);
            pk = *reinterpret_cast<const float4*>(Wk + qoff + kt + 32);
            pv = *reinterpret_cast<const float4*>(Wv + qoff + kt + 32);
            po = *reinterpret_cast<const float4*>(Wo + ooff + (size_t)(kt + 32) * D_DIM);
        }

#pragma unroll
        for (int kk = 0; kk < 32; kk++) {
            const float a0 = Ms[ty][kk],      a1 = Ms[ty + 16][kk];
            const float b0 = Ws[kk][tx],      b1 = Ws[kk][tx + 16];
            acc[0][0] += a0 * b0; acc[0][1] += a0 * b1;
            acc[1][0] += a1 * b0; acc[1][1] += a1 * b1;
        }
        __syncthreads();
    }
#pragma unroll
    for (int i = 0; i < 2; i++) {
        const int k = k0 + ty + i * 16;
        const int j = k & 15;
        const int kp = (k & ~15) | (4 * ((j & 7) >> 1) + 2 * (j >> 3) + (j & 1));
#pragma unroll
        for (int jj = 0; jj < 2; jj++) {
            const int n = n0 + tx + jj * 16;
            g_Wh[(size_t)n * D_DIM + kp] = __float2half_rn(acc[i][jj]);
        }
    }
}

// ---------------------------------------------------------------------------
// Main GEMM: out = x @ W_eff via fp16 mma.sync m16n8k16 (fp32 accum).
// BM=128, BN=112, BK=64 -> 7 mainloop iterations (half the barriers of R12).
// NSTG=2 double buffer, order: wait0 -> sync -> prefetch(it+1) -> compute(it).
// The sync proves iter it-1 finished, so the prefetch target ((it+1)&1 =
// it-1's buffer) is free; the prefetch covers one full BK=64 compute block.
// 256 threads (8 warps, 4m x 2n), warp tile 32x56.
// ---------------------------------------------------------------------------
__global__ void __launch_bounds__(256, 2) gemm_f16_kernel(const float* __restrict__ x,
                                                          float* __restrict__ out) {
    extern __shared__ __align__(16) char smem[];

    const int tid   = threadIdx.x;
    const int wid   = tid >> 5;
    const int lane  = tid & 31;
    const int g     = lane >> 2;
    const int t     = lane & 3;
    const int warpM = wid & 3;
    const int warpN = wid >> 2;

    const int m0 = blockIdx.y * BM;
    const int n0 = blockIdx.x * BN;

    const uint32_t smem_base = smem_u32(smem);

    float acc[2][7][4];
#pragma unroll
    for (int i = 0; i < 2; i++)
#pragma unroll
        for (int j = 0; j < 7; j++)
#pragma unroll
            for (int q = 0; q < 4; q++) acc[i][j][q] = 0.f;

    auto load_stage = [&](int s, int kt) {
        const uint32_t aBase = smem_base + (uint32_t)(s * STG_BYTES);
        const uint32_t bBase = aBase + (uint32_t)A_STAGE_BYTES;
        // A: 128 rows x 64 floats = 2048 16B chunks, 8 per thread
#pragma unroll
        for (int j = 0; j < 8; j++) {
            const int id  = tid + j * 256;
            const int row = id >> 4;
            const int c   = id & 15;
            CP16(aBase + (uint32_t)(row * (AS * 4) + c * 16),
                 x + (size_t)(m0 + row) * D_DIM + kt + c * 4);
        }
        // B: 112 rows x 64 halves (128B) = 896 16B chunks, 3 per thread + 128 extra
#pragma unroll
        for (int j = 0; j < 3; j++) {
            const int id  = tid + j * 256;
            const int row = id >> 3;
            const int c   = id & 7;
            CP16(bBase + (uint32_t)(row * BSB + c * 16),
                 (const char*)g_Wh + ((size_t)(n0 + row) * D_DIM + kt) * 2 + c * 16);
        }
        if (tid < 128) {
            const int id  = tid + 768;
            const int row = id >> 3;
            const int c   = id & 7;
            CP16(bBase + (uint32_t)(row * BSB + c * 16),
                 (const char*)g_Wh + ((size_t)(n0 + row) * D_DIM + kt) * 2 + c * 16);
        }
    };

    load_stage(0, 0);
    CP_COMMIT();

    const int NIT = D_DIM / BK;   // 7
#pragma unroll 1
    for (int it = 0; it < NIT; it++) {
        CP_WAIT0();          // stage it fully resident
        __syncthreads();     // all warps done with iter it-1 -> buffer (it+1)&1 free

        if (it + 1 < NIT) load_stage((it + 1) & 1, (it + 1) * BK);
        CP_COMMIT();

        const char* stage = smem + (it & 1) * STG_BYTES;
        const float* Arow = reinterpret_cast<const float*>(stage)
                            + (warpM * 32 + g) * AS;
        const char* Brow  = stage + A_STAGE_BYTES + (warpN * 56 + g) * BSB;

#pragma unroll
        for (int kk2 = 0; kk2 < 4; kk2++) {    // four k16 blocks per BK=64
            const int k0 = kk2 * 16;
            uint32_t af[2][4];
#pragma unroll
            for (int mi = 0; mi < 2; mi++) {
                const float* Ar = Arow + mi * 16 * AS;
                const float2 x0 = *reinterpret_cast<const float2*>(Ar + k0 + 2 * t);
                const float2 x1 = *reinterpret_cast<const float2*>(Ar + 8 * AS + k0 + 2 * t);
                const float2 x2 = *reinterpret_cast<const float2*>(Ar + k0 + 2 * t + 8);
                const float2 x3 = *reinterpret_cast<const float2*>(Ar + 8 * AS + k0 + 2 * t + 8);
                af[mi][0] = pack_h2(x0.x, x0.y);
                af[mi][1] = pack_h2(x1.x, x1.y);
                af[mi][2] = pack_h2(x2.x, x2.y);
                af[mi][3] = pack_h2(x3.x, x3.y);
            }
#pragma unroll
            for (int ni = 0; ni < 7; ni++) {
                // interleaved layout: 8B at byte offset kk2*32 + 8t
                const uint2 bv = *reinterpret_cast<const uint2*>(
                    Brow + ni * 8 * BSB + kk2 * 32 + 8 * t);
                mma_f16(acc[0][ni], af[0], bv.x, bv.y);
                mma_f16(acc[1][ni], af[1], bv.x, bv.y);
            }
        }
    }

    // ---- epilogue: rows (g, g+8), cols (2t, 2t+1) per (mi, ni)
#pragma unroll
    for (int mi = 0; mi < 2; mi++) {
        const int r0 = m0 + warpM * 32 + mi * 16 + g;
#pragma unroll
        for (int ni = 0; ni < 7; ni++) {
            const int c0 = n0 + warpN * 56 + ni * 8 + 2 * t;
            float2 v0, v1;
            v0.x = acc[mi][ni][0]; v0.y = acc[mi][ni][1];
            v1.x = acc[mi][ni][2]; v1.y = acc[mi][ni][3];
            *reinterpret_cast<float2*>(out + (size_t)r0 * D_DIM + c0)       = v0;
            *reinterpret_cast<float2*>(out + (size_t)(r0 + 8) * D_DIM + c0) = v1;
        }
    }
}

// ---------------------------------------------------------------------------
extern "C" void kernel_launch(void* const* d_in, const int* in_sizes, int n_in,
                              void* d_out, int out_size) {
    const float* x  = (const float*)d_in[0];
    const float* Wq = (const float*)d_in[1];
    const float* Wk = (const float*)d_in[2];
    const float* Wv = (const float*)d_in[3];
    const float* Wo = (const float*)d_in[4];
    const float* A  = (const float*)d_in[5];
    const float* B  = (const float*)d_in[6];
    const float* C  = (const float*)d_in[7];

    cudaFuncSetAttribute(gemm_f16_kernel, cudaFuncAttributeMaxDynamicSharedMemorySize,
                         SMEM_BYTES);

    weff_kernel<<<dim3(D_DIM / 32, D_DIM / 32), 256>>>(Wq, Wk, Wv, Wo, A, B, C);
    gemm_f16_kernel<<<dim3(D_DIM / BN, MTOT / BM), 256, SMEM_BYTES>>>(x, (float*)d_out);
}